// round 3
// baseline (speedup 1.0000x reference)
#include <cuda_runtime.h>
#include <cuda_bf16.h>
#include <math.h>

#define Bb 8
#define Kk 32
#define Hh 480
#define Ww 480
#define Nn 576
#define Dd 1024
#define CLSD 64
#define OUTD 256
#define INDIM 1093
#define BK 256

// ---- scratch (static device globals: allocation-free) ----
__device__ float    g_geom[BK * 5];
__device__ unsigned g_bits[BK * 18];     // 576-bit sample mask per (b,k)
__device__ int      g_cnt[BK];           // sample count (msum)
__device__ float    g_pooled[BK * Dd];
__device__ float    g_part[2 * BK * OUTD]; // split-i partials of layer1

// ============================================================
// Kernel 1: full-resolution mask scan -> geometry feats + sample bits
// grid = 256 blocks (one per b,k), 576 threads
// ============================================================
__global__ __launch_bounds__(576) void k_mask(const int* __restrict__ masks) {
    const int bk  = blockIdx.x;
    const int tid = threadIdx.x;
    const int4* mp = reinterpret_cast<const int4*>(masks + (size_t)bk * (Hh * Ww));

    unsigned area = 0, sx = 0, sy = 0;
    int xmn = Ww, xmx = -1, ymn = Hh, ymx = -1;

    // 57600 int4 chunks, 576 threads -> exactly 100 iterations
    #pragma unroll 4
    for (int it = 0; it < 100; it++) {
        int idx = tid + it * 576;
        int4 v = mp[idx];
        int h  = idx / 120;              // 120 int4 per row
        int w4 = (idx - h * 120) * 4;
        int o0 = v.x > 0, o1 = v.y > 0, o2 = v.z > 0, o3 = v.w > 0;
        int c  = o0 + o1 + o2 + o3;
        area += (unsigned)c;
        sy   += (unsigned)(h * c);
        sx   += (unsigned)(w4 * c + o1 + 2 * o2 + 3 * o3);
        if (c) {
            ymn = min(ymn, h); ymx = max(ymx, h);
            int first = o0 ? 0 : (o1 ? 1 : (o2 ? 2 : 3));
            int last  = o3 ? 3 : (o2 ? 2 : (o1 ? 1 : 0));
            xmn = min(xmn, w4 + first);
            xmx = max(xmx, w4 + last);
        }
    }

    // warp reduce
    #pragma unroll
    for (int off = 16; off; off >>= 1) {
        area += __shfl_down_sync(0xffffffffu, area, off);
        sx   += __shfl_down_sync(0xffffffffu, sx, off);
        sy   += __shfl_down_sync(0xffffffffu, sy, off);
        xmn = min(xmn, __shfl_down_sync(0xffffffffu, xmn, off));
        xmx = max(xmx, __shfl_down_sync(0xffffffffu, xmx, off));
        ymn = min(ymn, __shfl_down_sync(0xffffffffu, ymn, off));
        ymx = max(ymx, __shfl_down_sync(0xffffffffu, ymx, off));
    }

    __shared__ unsigned s_a[18], s_x[18], s_y[18];
    __shared__ int s_xmn[18], s_xmx[18], s_ymn[18], s_ymx[18];
    const int wid = tid >> 5, lid = tid & 31;
    if (lid == 0) {
        s_a[wid] = area; s_x[wid] = sx; s_y[wid] = sy;
        s_xmn[wid] = xmn; s_xmx[wid] = xmx; s_ymn[wid] = ymn; s_ymx[wid] = ymx;
    }
    __syncthreads();
    if (tid == 0) {
        unsigned At = 0, Xt = 0, Yt = 0;
        int xm = Ww, xM = -1, ym = Hh, yM = -1;
        for (int i = 0; i < 18; i++) {
            At += s_a[i]; Xt += s_x[i]; Yt += s_y[i];
            xm = min(xm, s_xmn[i]); xM = max(xM, s_xmx[i]);
            ym = min(ym, s_ymn[i]); yM = max(yM, s_ymx[i]);
        }
        float af   = (float)At;
        float safe = fmaxf(af, 1.0f);
        float cx = (float)Xt / safe * (1.0f / Ww);
        float cy = (float)Yt / safe * (1.0f / Hh);
        float bw = (float)(xM - xm + 1) * (1.0f / Ww);
        float bh = (float)(yM - ym + 1) * (1.0f / Hh);
        float an = af * (1.0f / (Hh * Ww));
        bool valid = (At >= 1);
        float* g = g_geom + bk * 5;
        g[0] = valid ? cx : 0.0f;
        g[1] = valid ? cy : 0.0f;
        g[2] = valid ? an : 0.0f;
        g[3] = valid ? bw : 0.0f;
        g[4] = valid ? bh : 0.0f;
    }

    // sampled 24x24 bits (nearest: src = 20*i, 20*j)
    __shared__ int s_cnt;
    if (tid == 0) s_cnt = 0;
    __syncthreads();
    {
        const int* mb = masks + (size_t)bk * (Hh * Ww);
        int i = tid / 24, j = tid - i * 24;
        int on = mb[(20 * i) * Ww + 20 * j] > 0;
        unsigned bal = __ballot_sync(0xffffffffu, on);
        if (lid == 0) {
            g_bits[bk * 18 + wid] = bal;
            atomicAdd(&s_cnt, __popc(bal));
        }
    }
    __syncthreads();
    if (tid == 0) g_cnt[bk] = s_cnt;
}

// ============================================================
// Kernel 2: masked pooling. Block = (d-chunk of 128, k-group of 8, b).
// Each fm element is read once per k-group (4x total) -> ~75MB L2.
// ============================================================
__global__ __launch_bounds__(128) void k_pool(const float* __restrict__ fm) {
    const int dc  = blockIdx.x;   // 0..7
    const int kg  = blockIdx.y;   // 0..3
    const int b   = blockIdx.z;   // 0..7
    const int tid = threadIdx.x;
    const int d   = dc * 128 + tid;
    const int k0  = kg * 8;

    __shared__ unsigned char s_sel[576];
    __shared__ float s_inv[8];

    for (int n = tid; n < 576; n += 128) {
        unsigned byte = 0;
        #pragma unroll
        for (int kk = 0; kk < 8; kk++) {
            unsigned word = g_bits[(b * Kk + k0 + kk) * 18 + (n >> 5)];
            byte |= ((word >> (n & 31)) & 1u) << kk;
        }
        s_sel[n] = (unsigned char)byte;
    }
    if (tid < 8) {
        int c = g_cnt[b * Kk + k0 + tid];
        s_inv[tid] = (c > 0) ? (1.0f / (float)c) : 0.0f;
    }
    __syncthreads();

    const float* fp = fm + (size_t)b * Nn * Dd + d;
    float a0 = 0.f, a1 = 0.f, a2 = 0.f, a3 = 0.f;
    float a4 = 0.f, a5 = 0.f, a6 = 0.f, a7 = 0.f;

    #pragma unroll 4
    for (int n = 0; n < 576; n++) {
        float f = __ldg(fp + (size_t)n * Dd);
        unsigned sel = s_sel[n];
        if (sel & 1u)   a0 += f;
        if (sel & 2u)   a1 += f;
        if (sel & 4u)   a2 += f;
        if (sel & 8u)   a3 += f;
        if (sel & 16u)  a4 += f;
        if (sel & 32u)  a5 += f;
        if (sel & 64u)  a6 += f;
        if (sel & 128u) a7 += f;
    }

    float* pp = g_pooled + (size_t)(b * Kk + k0) * Dd + d;
    pp[0 * Dd] = a0 * s_inv[0];
    pp[1 * Dd] = a1 * s_inv[1];
    pp[2 * Dd] = a2 * s_inv[2];
    pp[3 * Dd] = a3 * s_inv[3];
    pp[4 * Dd] = a4 * s_inv[4];
    pp[5 * Dd] = a5 * s_inv[5];
    pp[6 * Dd] = a6 * s_inv[6];
    pp[7 * Dd] = a7 * s_inv[7];
}

// ============================================================
// Kernel 3a: layer1 partial GEMM (split-i). grid = (2 halves, 64 row-groups)
// blockDim 256 (one thread per output column), 4 rows per block.
// ============================================================
__global__ __launch_bounds__(256) void k_mlp1(const float* __restrict__ W1,
                                              const void* __restrict__ cls_raw,
                                              const float* __restrict__ emb) {
    const int half = blockIdx.x;
    const int rg   = blockIdx.y;            // rows rg*4 .. rg*4+3
    const int j    = threadIdx.x;

    __shared__ alignas(16) float xs[4][1100];
    __shared__ int s_i32flag;

    // detect class_ids width: int64 (odd words zero) vs int32
    if (j == 0) s_i32flag = 0;
    __syncthreads();
    if (j < 128) {
        if (((const int*)cls_raw)[2 * j + 1] != 0) atomicOr(&s_i32flag, 1);
    }
    __syncthreads();
    const bool is64 = (s_i32flag == 0);

    #pragma unroll
    for (int r = 0; r < 4; r++) {
        const int row = rg * 4 + r;
        const float* pp = g_pooled + (size_t)row * Dd;
        for (int i = j; i < Dd; i += 256) xs[r][i] = pp[i];
        if (j < CLSD) {
            int c = is64 ? (int)((const long long*)cls_raw)[row]
                         : ((const int*)cls_raw)[row];
            xs[r][Dd + j] = emb[c * CLSD + j];
        }
        if (j < 5) xs[r][Dd + CLSD + j] = g_geom[row * 5 + j];
    }
    __syncthreads();

    const int i0 = half ? 548 : 0;
    const int i1 = half ? INDIM : 548;

    float a0 = 0.f, a1 = 0.f, a2 = 0.f, a3 = 0.f;
    int i = i0;
    #pragma unroll 2
    for (; i + 4 <= i1; i += 4) {
        float w0 = W1[(i + 0) * OUTD + j];
        float w1 = W1[(i + 1) * OUTD + j];
        float w2 = W1[(i + 2) * OUTD + j];
        float w3 = W1[(i + 3) * OUTD + j];
        float4 x0 = *(const float4*)&xs[0][i];
        float4 x1 = *(const float4*)&xs[1][i];
        float4 x2 = *(const float4*)&xs[2][i];
        float4 x3 = *(const float4*)&xs[3][i];
        a0 = fmaf(x0.x, w0, a0); a0 = fmaf(x0.y, w1, a0);
        a0 = fmaf(x0.z, w2, a0); a0 = fmaf(x0.w, w3, a0);
        a1 = fmaf(x1.x, w0, a1); a1 = fmaf(x1.y, w1, a1);
        a1 = fmaf(x1.z, w2, a1); a1 = fmaf(x1.w, w3, a1);
        a2 = fmaf(x2.x, w0, a2); a2 = fmaf(x2.y, w1, a2);
        a2 = fmaf(x2.z, w2, a2); a2 = fmaf(x2.w, w3, a2);
        a3 = fmaf(x3.x, w0, a3); a3 = fmaf(x3.y, w1, a3);
        a3 = fmaf(x3.z, w2, a3); a3 = fmaf(x3.w, w3, a3);
    }
    for (; i < i1; i++) {
        float w = W1[i * OUTD + j];
        a0 = fmaf(xs[0][i], w, a0);
        a1 = fmaf(xs[1][i], w, a1);
        a2 = fmaf(xs[2][i], w, a2);
        a3 = fmaf(xs[3][i], w, a3);
    }

    float* gp = g_part + (size_t)half * BK * OUTD + (size_t)(rg * 4) * OUTD + j;
    gp[0 * OUTD] = a0;
    gp[1 * OUTD] = a1;
    gp[2 * OUTD] = a2;
    gp[3 * OUTD] = a3;
}

// ============================================================
// Kernel 3b: combine halves + bias + exact GELU + LayerNorm + layer2.
// grid = 64 blocks (4 rows each), blockDim 256.
// ============================================================
__global__ __launch_bounds__(256) void k_mlp2(const float* __restrict__ b1,
                                              const float* __restrict__ ln_g,
                                              const float* __restrict__ ln_b,
                                              const float* __restrict__ W2,
                                              const float* __restrict__ b2,
                                              float* __restrict__ out) {
    const int rg = blockIdx.x;
    const int j  = threadIdx.x;

    __shared__ alignas(16) float hn[4][OUTD];
    __shared__ float red[4][2][8];
    __shared__ float mu_s[4], is_s[4];

    float h[4];
    const float bb = b1[j];
    #pragma unroll
    for (int r = 0; r < 4; r++) {
        const int row = rg * 4 + r;
        float v = g_part[(size_t)row * OUTD + j] +
                  g_part[(size_t)(BK + row) * OUTD + j] + bb;
        // exact gelu: 0.5*x*(1+erf(x/sqrt(2)))
        v = 0.5f * v * (1.0f + erff(v * 0.7071067811865476f));
        h[r] = v;
    }

    #pragma unroll
    for (int r = 0; r < 4; r++) {
        float s = h[r], s2 = h[r] * h[r];
        #pragma unroll
        for (int off = 16; off; off >>= 1) {
            s  += __shfl_down_sync(0xffffffffu, s, off);
            s2 += __shfl_down_sync(0xffffffffu, s2, off);
        }
        if ((j & 31) == 0) { red[r][0][j >> 5] = s; red[r][1][j >> 5] = s2; }
    }
    __syncthreads();
    if (j < 4) {
        float s = 0.f, s2 = 0.f;
        #pragma unroll
        for (int w = 0; w < 8; w++) { s += red[j][0][w]; s2 += red[j][1][w]; }
        float mu  = s * (1.0f / OUTD);
        float var = s2 * (1.0f / OUTD) - mu * mu;
        mu_s[j] = mu;
        is_s[j] = rsqrtf(var + 1e-5f);
    }
    __syncthreads();

    const float g = ln_g[j], bt = ln_b[j];
    #pragma unroll
    for (int r = 0; r < 4; r++)
        hn[r][j] = (h[r] - mu_s[r]) * is_s[r] * g + bt;
    __syncthreads();

    const float bo = b2[j];
    float o0 = bo, o1 = bo, o2 = bo, o3 = bo;
    #pragma unroll 2
    for (int i = 0; i < OUTD; i += 4) {
        float w0 = W2[(i + 0) * OUTD + j];
        float w1 = W2[(i + 1) * OUTD + j];
        float w2 = W2[(i + 2) * OUTD + j];
        float w3 = W2[(i + 3) * OUTD + j];
        float4 h0 = *(const float4*)&hn[0][i];
        float4 h1 = *(const float4*)&hn[1][i];
        float4 h2 = *(const float4*)&hn[2][i];
        float4 h3 = *(const float4*)&hn[3][i];
        o0 = fmaf(h0.x, w0, o0); o0 = fmaf(h0.y, w1, o0);
        o0 = fmaf(h0.z, w2, o0); o0 = fmaf(h0.w, w3, o0);
        o1 = fmaf(h1.x, w0, o1); o1 = fmaf(h1.y, w1, o1);
        o1 = fmaf(h1.z, w2, o1); o1 = fmaf(h1.w, w3, o1);
        o2 = fmaf(h2.x, w0, o2); o2 = fmaf(h2.y, w1, o2);
        o2 = fmaf(h2.z, w2, o2); o2 = fmaf(h2.w, w3, o2);
        o3 = fmaf(h3.x, w0, o3); o3 = fmaf(h3.y, w1, o3);
        o3 = fmaf(h3.z, w2, o3); o3 = fmaf(h3.w, w3, o3);
    }

    float* op = out + (size_t)(rg * 4) * OUTD + j;
    op[0 * OUTD] = o0;
    op[1 * OUTD] = o1;
    op[2 * OUTD] = o2;
    op[3 * OUTD] = o3;
}

// ============================================================
extern "C" void kernel_launch(void* const* d_in, const int* in_sizes, int n_in,
                              void* d_out, int out_size) {
    const float* fm    = (const float*)d_in[0];
    const int*   masks = (const int*)d_in[1];
    const void*  cls   = d_in[2];
    const float* emb   = (const float*)d_in[3];
    const float* W1    = (const float*)d_in[4];
    const float* b1    = (const float*)d_in[5];
    const float* lg    = (const float*)d_in[6];
    const float* lb    = (const float*)d_in[7];
    const float* W2    = (const float*)d_in[8];
    const float* b2    = (const float*)d_in[9];
    float* out = (float*)d_out;

    k_mask<<<BK, 576>>>(masks);
    k_pool<<<dim3(8, 4, 8), 128>>>(fm);
    k_mlp1<<<dim3(2, 64), 256>>>(W1, cls, emb);
    k_mlp2<<<64, 256>>>(b1, lg, lb, W2, b2, out);
}

// round 4
// speedup vs baseline: 1.0122x; 1.0122x over previous
#include <cuda_runtime.h>
#include <cuda_bf16.h>
#include <math.h>

#define Bb 8
#define Kk 32
#define Hh 480
#define Ww 480
#define Nn 576
#define Dd 1024
#define CLSD 64
#define OUTD 256
#define INDIM 1093
#define BK 256

// ---- scratch (static device globals: allocation-free) ----
__device__ float    g_geom[BK * 5];
__device__ unsigned g_bits[BK * 18];         // 576-bit sample mask per (b,k)
__device__ int      g_cnt[BK];               // sample count
__device__ float    g_pooled[BK * Dd];
__device__ float    g_part[4 * BK * OUTD];   // 4-way split-i partials of layer1

// ============================================================
// Kernel 1: full-res mask scan -> geometry feats + sample bits
// grid = 256 blocks (one per b,k), 576 threads. DRAM-bound (~236MB).
// ============================================================
__global__ __launch_bounds__(576) void k_mask(const int* __restrict__ masks) {
    const int bk  = blockIdx.x;
    const int tid = threadIdx.x;
    const int4* mp = reinterpret_cast<const int4*>(masks + (size_t)bk * (Hh * Ww));

    unsigned area = 0, sx = 0, sy = 0;
    int xmn = Ww, xmx = -1, ymn = Hh, ymx = -1;

    #pragma unroll 4
    for (int it = 0; it < 100; it++) {
        int idx = tid + it * 576;
        int4 v = mp[idx];
        int h  = idx / 120;                  // 120 int4 per row
        int w4 = (idx - h * 120) * 4;
        int o0 = v.x > 0, o1 = v.y > 0, o2 = v.z > 0, o3 = v.w > 0;
        int c  = o0 + o1 + o2 + o3;
        area += (unsigned)c;
        sy   += (unsigned)(h * c);
        sx   += (unsigned)(w4 * c + o1 + 2 * o2 + 3 * o3);
        if (c) {
            ymn = min(ymn, h); ymx = max(ymx, h);
            int first = o0 ? 0 : (o1 ? 1 : (o2 ? 2 : 3));
            int last  = o3 ? 3 : (o2 ? 2 : (o1 ? 1 : 0));
            xmn = min(xmn, w4 + first);
            xmx = max(xmx, w4 + last);
        }
    }

    #pragma unroll
    for (int off = 16; off; off >>= 1) {
        area += __shfl_down_sync(0xffffffffu, area, off);
        sx   += __shfl_down_sync(0xffffffffu, sx, off);
        sy   += __shfl_down_sync(0xffffffffu, sy, off);
        xmn = min(xmn, __shfl_down_sync(0xffffffffu, xmn, off));
        xmx = max(xmx, __shfl_down_sync(0xffffffffu, xmx, off));
        ymn = min(ymn, __shfl_down_sync(0xffffffffu, ymn, off));
        ymx = max(ymx, __shfl_down_sync(0xffffffffu, ymx, off));
    }

    __shared__ unsigned s_a[18], s_x[18], s_y[18];
    __shared__ int s_xmn[18], s_xmx[18], s_ymn[18], s_ymx[18];
    const int wid = tid >> 5, lid = tid & 31;
    if (lid == 0) {
        s_a[wid] = area; s_x[wid] = sx; s_y[wid] = sy;
        s_xmn[wid] = xmn; s_xmx[wid] = xmx; s_ymn[wid] = ymn; s_ymx[wid] = ymx;
    }
    __syncthreads();
    if (tid == 0) {
        unsigned At = 0, Xt = 0, Yt = 0;
        int xm = Ww, xM = -1, ym = Hh, yM = -1;
        for (int i = 0; i < 18; i++) {
            At += s_a[i]; Xt += s_x[i]; Yt += s_y[i];
            xm = min(xm, s_xmn[i]); xM = max(xM, s_xmx[i]);
            ym = min(ym, s_ymn[i]); yM = max(yM, s_ymx[i]);
        }
        float af   = (float)At;
        float safe = fmaxf(af, 1.0f);
        float cx = (float)Xt / safe * (1.0f / Ww);
        float cy = (float)Yt / safe * (1.0f / Hh);
        float bw = (float)(xM - xm + 1) * (1.0f / Ww);
        float bh = (float)(yM - ym + 1) * (1.0f / Hh);
        float an = af * (1.0f / (Hh * Ww));
        bool valid = (At >= 1);
        float* g = g_geom + bk * 5;
        g[0] = valid ? cx : 0.0f;
        g[1] = valid ? cy : 0.0f;
        g[2] = valid ? an : 0.0f;
        g[3] = valid ? bw : 0.0f;
        g[4] = valid ? bh : 0.0f;
    }

    // sampled 24x24 bits (nearest: src = 20*i, 20*j)
    __shared__ int s_cnt;
    if (tid == 0) s_cnt = 0;
    __syncthreads();
    {
        const int* mb = masks + (size_t)bk * (Hh * Ww);
        int i = tid / 24, j = tid - i * 24;
        int on = mb[(20 * i) * Ww + 20 * j] > 0;
        unsigned bal = __ballot_sync(0xffffffffu, on);
        if (lid == 0) {
            g_bits[bk * 18 + wid] = bal;
            atomicAdd(&s_cnt, __popc(bal));
        }
    }
    __syncthreads();
    if (tid == 0) g_cnt[bk] = s_cnt;
}

// ============================================================
// Kernel 2: masked pooling via 0/1 float multipliers (FFMA, no predication).
// grid = (4 d-chunks of 256, 4 k-groups of 8, 8 b) = 128 blocks, 256 thr.
// Per point: 1 LDG + 2 LDS.128 (broadcast) + 8 FFMA.
// ============================================================
__global__ __launch_bounds__(256) void k_pool(const float* __restrict__ fm) {
    const int dc  = blockIdx.x;   // 0..3
    const int kg  = blockIdx.y;   // 0..3
    const int b   = blockIdx.z;   // 0..7
    const int tid = threadIdx.x;
    const int d   = dc * 256 + tid;
    const int k0  = kg * 8;

    __shared__ alignas(16) float4 s_m[Nn][2];   // 18KB: 8 masks as 0/1 floats
    __shared__ float s_inv[8];

    for (int n = tid; n < Nn; n += 256) {
        float mk[8];
        #pragma unroll
        for (int kk = 0; kk < 8; kk++) {
            unsigned word = g_bits[(b * Kk + k0 + kk) * 18 + (n >> 5)];
            mk[kk] = ((word >> (n & 31)) & 1u) ? 1.0f : 0.0f;
        }
        s_m[n][0] = make_float4(mk[0], mk[1], mk[2], mk[3]);
        s_m[n][1] = make_float4(mk[4], mk[5], mk[6], mk[7]);
    }
    if (tid < 8) {
        int c = g_cnt[b * Kk + k0 + tid];
        s_inv[tid] = (c > 0) ? (1.0f / (float)c) : 0.0f;
    }
    __syncthreads();

    const float* fp = fm + (size_t)b * Nn * Dd + d;
    float a0 = 0.f, a1 = 0.f, a2 = 0.f, a3 = 0.f;
    float a4 = 0.f, a5 = 0.f, a6 = 0.f, a7 = 0.f;

    #pragma unroll 4
    for (int n = 0; n < Nn; n++) {
        float f = __ldg(fp + (size_t)n * Dd);
        float4 m0 = s_m[n][0];
        float4 m1 = s_m[n][1];
        a0 = fmaf(f, m0.x, a0);
        a1 = fmaf(f, m0.y, a1);
        a2 = fmaf(f, m0.z, a2);
        a3 = fmaf(f, m0.w, a3);
        a4 = fmaf(f, m1.x, a4);
        a5 = fmaf(f, m1.y, a5);
        a6 = fmaf(f, m1.z, a6);
        a7 = fmaf(f, m1.w, a7);
    }

    float* pp = g_pooled + (size_t)(b * Kk + k0) * Dd + d;
    pp[0 * Dd] = a0 * s_inv[0];
    pp[1 * Dd] = a1 * s_inv[1];
    pp[2 * Dd] = a2 * s_inv[2];
    pp[3 * Dd] = a3 * s_inv[3];
    pp[4 * Dd] = a4 * s_inv[4];
    pp[5 * Dd] = a5 * s_inv[5];
    pp[6 * Dd] = a6 * s_inv[6];
    pp[7 * Dd] = a7 * s_inv[7];
}

// ============================================================
// Kernel 3a: layer1 partial GEMM, 4-way split-i.
// grid = (4 splits, 32 row-groups of 8), 256 threads (one per out col).
// Split boundaries: 0,276,552,828,1093 (first three %4 == 0 for float4).
// ============================================================
__global__ __launch_bounds__(256) void k_mlp1(const float* __restrict__ W1,
                                              const void* __restrict__ cls_raw,
                                              const float* __restrict__ emb) {
    const int split = blockIdx.x;            // 0..3
    const int rg    = blockIdx.y;            // rows rg*8 .. rg*8+7
    const int j     = threadIdx.x;

    const int i0  = split * 276;
    const int i1  = (split == 3) ? INDIM : (i0 + 276);
    const int len = i1 - i0;

    __shared__ alignas(16) float xs[8][280];
    __shared__ int s_i32flag;

    if (j == 0) s_i32flag = 0;
    __syncthreads();
    if (j < 128) {
        if (((const int*)cls_raw)[2 * j + 1] != 0) atomicOr(&s_i32flag, 1);
    }
    __syncthreads();
    const bool is64 = (s_i32flag == 0);

    #pragma unroll
    for (int r = 0; r < 8; r++) {
        const int row = rg * 8 + r;
        int c = is64 ? (int)((const long long*)cls_raw)[row]
                     : ((const int*)cls_raw)[row];
        for (int t = j; t < len; t += 256) {
            int gi = i0 + t;
            float v;
            if (gi < Dd)                 v = g_pooled[(size_t)row * Dd + gi];
            else if (gi < Dd + CLSD)     v = emb[c * CLSD + (gi - Dd)];
            else                         v = g_geom[row * 5 + (gi - Dd - CLSD)];
            xs[r][t] = v;
        }
    }
    __syncthreads();

    const float* wp = W1 + (size_t)i0 * OUTD + j;
    float a[8];
    #pragma unroll
    for (int r = 0; r < 8; r++) a[r] = 0.f;

    int t = 0;
    for (; t + 4 <= len; t += 4) {
        float w0 = wp[(size_t)(t + 0) * OUTD];
        float w1 = wp[(size_t)(t + 1) * OUTD];
        float w2 = wp[(size_t)(t + 2) * OUTD];
        float w3 = wp[(size_t)(t + 3) * OUTD];
        #pragma unroll
        for (int r = 0; r < 8; r++) {
            float4 x = *(const float4*)&xs[r][t];
            a[r] = fmaf(x.x, w0, a[r]);
            a[r] = fmaf(x.y, w1, a[r]);
            a[r] = fmaf(x.z, w2, a[r]);
            a[r] = fmaf(x.w, w3, a[r]);
        }
    }
    for (; t < len; t++) {
        float w = wp[(size_t)t * OUTD];
        #pragma unroll
        for (int r = 0; r < 8; r++) a[r] = fmaf(xs[r][t], w, a[r]);
    }

    float* gp = g_part + (size_t)split * BK * OUTD + (size_t)(rg * 8) * OUTD + j;
    #pragma unroll
    for (int r = 0; r < 8; r++) gp[(size_t)r * OUTD] = a[r];
}

// ============================================================
// Kernel 3b: combine 4 partials + bias + exact GELU + LayerNorm + layer2.
// grid = 128 blocks (2 rows each), 256 threads.
// ============================================================
__global__ __launch_bounds__(256) void k_mlp2(const float* __restrict__ b1,
                                              const float* __restrict__ ln_g,
                                              const float* __restrict__ ln_b,
                                              const float* __restrict__ W2,
                                              const float* __restrict__ b2,
                                              float* __restrict__ out) {
    const int rg = blockIdx.x;               // rows rg*2, rg*2+1
    const int j  = threadIdx.x;

    __shared__ alignas(16) float hn[2][OUTD];
    __shared__ float red[2][2][8];
    __shared__ float mu_s[2], is_s[2];

    float h[2];
    const float bb = b1[j];
    #pragma unroll
    for (int r = 0; r < 2; r++) {
        const int row = rg * 2 + r;
        float v = g_part[(size_t)row * OUTD + j]
                + g_part[(size_t)(BK + row) * OUTD + j]
                + g_part[(size_t)(2 * BK + row) * OUTD + j]
                + g_part[(size_t)(3 * BK + row) * OUTD + j] + bb;
        v = 0.5f * v * (1.0f + erff(v * 0.7071067811865476f));
        h[r] = v;
    }

    #pragma unroll
    for (int r = 0; r < 2; r++) {
        float s = h[r], s2 = h[r] * h[r];
        #pragma unroll
        for (int off = 16; off; off >>= 1) {
            s  += __shfl_down_sync(0xffffffffu, s, off);
            s2 += __shfl_down_sync(0xffffffffu, s2, off);
        }
        if ((j & 31) == 0) { red[r][0][j >> 5] = s; red[r][1][j >> 5] = s2; }
    }
    __syncthreads();
    if (j < 2) {
        float s = 0.f, s2 = 0.f;
        #pragma unroll
        for (int w = 0; w < 8; w++) { s += red[j][0][w]; s2 += red[j][1][w]; }
        float mu  = s * (1.0f / OUTD);
        float var = s2 * (1.0f / OUTD) - mu * mu;
        mu_s[j] = mu;
        is_s[j] = rsqrtf(var + 1e-5f);
    }
    __syncthreads();

    const float g = ln_g[j], bt = ln_b[j];
    #pragma unroll
    for (int r = 0; r < 2; r++)
        hn[r][j] = (h[r] - mu_s[r]) * is_s[r] * g + bt;
    __syncthreads();

    const float bo = b2[j];
    float o0 = bo, o1 = bo;
    #pragma unroll 4
    for (int i = 0; i < OUTD; i += 4) {
        float w0 = W2[(i + 0) * OUTD + j];
        float w1 = W2[(i + 1) * OUTD + j];
        float w2 = W2[(i + 2) * OUTD + j];
        float w3 = W2[(i + 3) * OUTD + j];
        float4 h0 = *(const float4*)&hn[0][i];
        float4 h1 = *(const float4*)&hn[1][i];
        o0 = fmaf(h0.x, w0, o0); o0 = fmaf(h0.y, w1, o0);
        o0 = fmaf(h0.z, w2, o0); o0 = fmaf(h0.w, w3, o0);
        o1 = fmaf(h1.x, w0, o1); o1 = fmaf(h1.y, w1, o1);
        o1 = fmaf(h1.z, w2, o1); o1 = fmaf(h1.w, w3, o1);
    }

    float* op = out + (size_t)(rg * 2) * OUTD + j;
    op[0 * OUTD] = o0;
    op[1 * OUTD] = o1;
}

// ============================================================
extern "C" void kernel_launch(void* const* d_in, const int* in_sizes, int n_in,
                              void* d_out, int out_size) {
    const float* fm    = (const float*)d_in[0];
    const int*   masks = (const int*)d_in[1];
    const void*  cls   = d_in[2];
    const float* emb   = (const float*)d_in[3];
    const float* W1    = (const float*)d_in[4];
    const float* b1    = (const float*)d_in[5];
    const float* lg    = (const float*)d_in[6];
    const float* lb    = (const float*)d_in[7];
    const float* W2    = (const float*)d_in[8];
    const float* b2    = (const float*)d_in[9];
    float* out = (float*)d_out;

    k_mask<<<BK, 576>>>(masks);
    k_pool<<<dim3(4, 4, 8), 256>>>(fm);
    k_mlp1<<<dim3(4, 32), 256>>>(W1, cls, emb);
    k_mlp2<<<128, 256>>>(b1, lg, lb, W2, b2, out);
}

// round 6
// speedup vs baseline: 1.6654x; 1.6453x over previous
#include <cuda_runtime.h>
#include <cuda_bf16.h>
#include <math.h>

#define Kk 32
#define Hh 480
#define Ww 480
#define Nn 576
#define Dd 1024
#define CLSD 64
#define OUTD 256
#define INDIM 1093
#define BK 256
#define XS 1096   // padded row stride of assembled x

// ---- scratch (static device globals: allocation-free) ----
__device__ int      g_stat[BK][8];        // area, sx, sy, xmn, xmx, ymn, ymx
__device__ unsigned g_bits[BK * 18];      // 576-bit sample mask per (b,k)
__device__ int      g_cnt[BK];
__device__ float    g_x[BK * XS];         // assembled [pooled | cls | geom]
__device__ float    g_part[4 * BK * OUTD];

// ============================================================
// Kernel 0: init stats, sample bits, class-embedding gather.
// grid = 256 (one per b,k), 576 threads (24x24 sample grid).
// ============================================================
__global__ __launch_bounds__(576) void k_init(const int* __restrict__ masks,
                                              const void* __restrict__ cls_raw,
                                              const float* __restrict__ emb) {
    const int bk  = blockIdx.x;
    const int tid = threadIdx.x;
    const int wid = tid >> 5, lid = tid & 31;
    __shared__ int s_flag, s_cnt;
    if (tid == 0) { s_flag = 0; s_cnt = 0; }
    if (tid < 8) {
        int v = 0;
        if (tid == 3 || tid == 5) v = 1 << 29;   // xmn, ymn init BIG
        if (tid == 4 || tid == 6) v = -1;        // xmx, ymx init
        g_stat[bk][tid] = v;
    }
    __syncthreads();
    // detect int64 vs int32 class_ids (odd 32-bit words all zero => int64)
    if (tid < 128) {
        if (((const int*)cls_raw)[2 * tid + 1] != 0) atomicOr(&s_flag, 1);
    }
    // sampled 24x24 bits (nearest: src = 20*i, 20*j)
    const int* mb = masks + (size_t)bk * (Hh * Ww);
    int i = tid / 24, j = tid - i * 24;
    int on = mb[(20 * i) * Ww + 20 * j] > 0;
    unsigned bal = __ballot_sync(0xffffffffu, on);
    if (lid == 0) { g_bits[bk * 18 + wid] = bal; atomicAdd(&s_cnt, __popc(bal)); }
    __syncthreads();
    if (tid == 0) g_cnt[bk] = s_cnt;
    const bool is64 = (s_flag == 0);
    int c = is64 ? (int)((const long long*)cls_raw)[bk]
                 : ((const int*)cls_raw)[bk];
    if (tid < CLSD) g_x[(size_t)bk * XS + Dd + tid] = emb[c * CLSD + tid];
}

// ============================================================
// Kernel 1: full-res mask stats. Branch-free, division-free, fully unrolled
// => 30 front-batched LDG.128 per thread, DRAM-bound.
// grid = (4 row-chunks, 256 bk), 480 threads.
// Thread owns a fixed int4-column (col4 = tid%120), rows stride 4.
// NOTE: mask values are {0,1}; used directly as indicators.
// ============================================================
__global__ __launch_bounds__(480) void k_mask(const int* __restrict__ masks) {
    const int chunk = blockIdx.x;          // 0..3 (120 rows each)
    const int bk    = blockIdx.y;
    const int tid   = threadIdx.x;
    const int col4  = tid % 120;
    const int rowg  = tid / 120;           // 0..3
    const int h0    = chunk * 120 + rowg;
    const int4* mp  = reinterpret_cast<const int4*>(masks + (size_t)bk * (Hh * Ww))
                      + (size_t)h0 * 120 + col4;

    int area = 0, itc = 0, sxo = 0, occ = 0;
    int ymni = 1000, ymxi = -1;
    #pragma unroll
    for (int it = 0; it < 30; it++) {
        int4 v = __ldg(&mp[(size_t)it * 480]);
        int c = v.x + v.y + v.z + v.w;
        area += c;
        itc  += c * it;
        sxo  += v.y + 2 * v.z + 3 * v.w;
        occ  |= v.x + 2 * v.y + 4 * v.z + 8 * v.w;
        ymni = min(ymni, c ? it : 1000);
        ymxi = max(ymxi, c ? it : -1);
    }
    const int w4 = col4 * 4;
    int sx = w4 * area + sxo;
    int sy = h0 * area + 4 * itc;
    int xmn = occ ? (w4 + __ffs(occ) - 1)  : (1 << 29);
    int xmx = occ ? (w4 + 31 - __clz(occ)) : -1;
    int ymn = (ymxi >= 0) ? (h0 + 4 * ymni) : (1 << 29);
    int ymx = (ymxi >= 0) ? (h0 + 4 * ymxi) : -1;

    #pragma unroll
    for (int off = 16; off; off >>= 1) {
        area += __shfl_down_sync(0xffffffffu, area, off);
        sx   += __shfl_down_sync(0xffffffffu, sx, off);
        sy   += __shfl_down_sync(0xffffffffu, sy, off);
        xmn = min(xmn, __shfl_down_sync(0xffffffffu, xmn, off));
        xmx = max(xmx, __shfl_down_sync(0xffffffffu, xmx, off));
        ymn = min(ymn, __shfl_down_sync(0xffffffffu, ymn, off));
        ymx = max(ymx, __shfl_down_sync(0xffffffffu, ymx, off));
    }
    __shared__ int sA[15], sX[15], sY[15], sxm[15], sxM[15], sym[15], syM[15];
    const int wid = tid >> 5, lid = tid & 31;
    if (lid == 0) {
        sA[wid] = area; sX[wid] = sx; sY[wid] = sy;
        sxm[wid] = xmn; sxM[wid] = xmx; sym[wid] = ymn; syM[wid] = ymx;
    }
    __syncthreads();
    if (tid == 0) {
        int A = 0, X = 0, Y = 0, xm = 1 << 29, xM = -1, ym = 1 << 29, yM = -1;
        #pragma unroll
        for (int i = 0; i < 15; i++) {
            A += sA[i]; X += sX[i]; Y += sY[i];
            xm = min(xm, sxm[i]); xM = max(xM, sxM[i]);
            ym = min(ym, sym[i]); yM = max(yM, syM[i]);
        }
        atomicAdd(&g_stat[bk][0], A);
        atomicAdd(&g_stat[bk][1], X);
        atomicAdd(&g_stat[bk][2], Y);
        atomicMin(&g_stat[bk][3], xm);
        atomicMax(&g_stat[bk][4], xM);
        atomicMin(&g_stat[bk][5], ym);
        atomicMax(&g_stat[bk][6], yM);
    }
}

// ============================================================
// Kernel 2: masked pooling via SMEM-staged fm tiles + 0/1 multipliers.
// grid = (4 d-chunks, 4 k-groups of 8, 8 b), 256 threads.
// Also finalizes geometry into g_x (needs k_mask stats).
// ============================================================
__global__ __launch_bounds__(256) void k_pool(const float* __restrict__ fm) {
    const int dc  = blockIdx.x;   // 0..3
    const int kg  = blockIdx.y;   // 0..3
    const int b   = blockIdx.z;   // 0..7
    const int tid = threadIdx.x;
    const int d   = dc * 256 + tid;
    const int k0  = kg * 8;

    __shared__ alignas(16) float4 s_m[Nn][2];      // 18.4 KB
    __shared__ alignas(16) float  s_f[24][256];    // 24 KB
    __shared__ float s_inv[8];

    // geometry finalize (stats written by k_mask)
    if (dc == 0 && kg == 0 && tid < Kk) {
        const int bk = b * Kk + tid;
        int A = g_stat[bk][0], SX = g_stat[bk][1], SY = g_stat[bk][2];
        int xm = g_stat[bk][3], xM = g_stat[bk][4];
        int ym = g_stat[bk][5], yM = g_stat[bk][6];
        float af = (float)A, safe = fmaxf(af, 1.0f);
        bool valid = (A >= 1);
        float* gx = g_x + (size_t)bk * XS + Dd + CLSD;
        gx[0] = valid ? (float)SX / safe * (1.0f / Ww) : 0.0f;
        gx[1] = valid ? (float)SY / safe * (1.0f / Hh) : 0.0f;
        gx[2] = valid ? af * (1.0f / (Hh * Ww)) : 0.0f;
        gx[3] = valid ? (float)(xM - xm + 1) * (1.0f / Ww) : 0.0f;
        gx[4] = valid ? (float)(yM - ym + 1) * (1.0f / Hh) : 0.0f;
    }

    for (int n = tid; n < Nn; n += 256) {
        float mk[8];
        #pragma unroll
        for (int kk = 0; kk < 8; kk++) {
            unsigned word = g_bits[(b * Kk + k0 + kk) * 18 + (n >> 5)];
            mk[kk] = ((word >> (n & 31)) & 1u) ? 1.0f : 0.0f;
        }
        s_m[n][0] = make_float4(mk[0], mk[1], mk[2], mk[3]);
        s_m[n][1] = make_float4(mk[4], mk[5], mk[6], mk[7]);
    }
    if (tid < 8) {
        int c = g_cnt[b * Kk + k0 + tid];
        s_inv[tid] = (c > 0) ? (1.0f / (float)c) : 0.0f;
    }
    __syncthreads();

    float a0 = 0.f, a1 = 0.f, a2 = 0.f, a3 = 0.f;
    float a4 = 0.f, a5 = 0.f, a6 = 0.f, a7 = 0.f;
    const float* fb = fm + (size_t)b * Nn * Dd;
    const int r4 = tid >> 6, c4 = tid & 63;       // for float4 tile loads

    for (int n0 = 0; n0 < Nn; n0 += 24) {
        // cooperative batched load of 24x256 fm tile (6 independent LDG.128/thread)
        const float4* src = reinterpret_cast<const float4*>(fb + (size_t)n0 * Dd) + dc * 64;
        float4* dst = reinterpret_cast<float4*>(s_f);
        #pragma unroll
        for (int p = 0; p < 6; p++) {
            int r = r4 + p * 4;
            dst[r * 64 + c4] = src[(size_t)r * 256 + c4];
        }
        __syncthreads();
        #pragma unroll 8
        for (int r2 = 0; r2 < 24; r2++) {
            float f = s_f[r2][tid];
            float4 m0 = s_m[n0 + r2][0];
            float4 m1 = s_m[n0 + r2][1];
            a0 = fmaf(f, m0.x, a0); a1 = fmaf(f, m0.y, a1);
            a2 = fmaf(f, m0.z, a2); a3 = fmaf(f, m0.w, a3);
            a4 = fmaf(f, m1.x, a4); a5 = fmaf(f, m1.y, a5);
            a6 = fmaf(f, m1.z, a6); a7 = fmaf(f, m1.w, a7);
        }
        __syncthreads();
    }

    float* pp = g_x + (size_t)(b * Kk + k0) * XS + d;
    pp[0 * XS] = a0 * s_inv[0];
    pp[1 * XS] = a1 * s_inv[1];
    pp[2 * XS] = a2 * s_inv[2];
    pp[3 * XS] = a3 * s_inv[3];
    pp[4 * XS] = a4 * s_inv[4];
    pp[5 * XS] = a5 * s_inv[5];
    pp[6 * XS] = a6 * s_inv[6];
    pp[7 * XS] = a7 * s_inv[7];
}

// ============================================================
// Kernel 3a: layer1 partial GEMM, 4-way split-i, SMEM-staged W1 tiles.
// grid = (4 splits, 32 row-groups of 8), 256 threads.
// ============================================================
__global__ __launch_bounds__(256) void k_mlp1(const float* __restrict__ W1) {
    const int split = blockIdx.x;
    const int rg    = blockIdx.y;
    const int j     = threadIdx.x;
    const int i0    = split * 276;
    const int len   = (split == 3) ? (INDIM - 828) : 276;   // 276 or 265

    __shared__ alignas(16) float xs[8][280];
    __shared__ float sw[36][256];                           // 36 KB

    #pragma unroll
    for (int r = 0; r < 8; r++) {
        const float* src = g_x + (size_t)(rg * 8 + r) * XS + i0;
        for (int t = j; t < len; t += 256) xs[r][t] = src[t];
    }

    float a[8];
    #pragma unroll
    for (int r = 0; r < 8; r++) a[r] = 0.f;

    int done = 0;
    while (done < len) {
        int cur = min(36, len - done);
        // batched coalesced W1 tile load (<=36 independent LDGs/thread)
        for (int i = 0; i < cur; i++)
            sw[i][j] = W1[(size_t)(i0 + done + i) * OUTD + j];
        __syncthreads();   // also covers xs on first pass
        int i = 0;
        for (; i + 4 <= cur; i += 4) {
            float w0 = sw[i + 0][j], w1 = sw[i + 1][j];
            float w2 = sw[i + 2][j], w3 = sw[i + 3][j];
            #pragma unroll
            for (int r = 0; r < 8; r++) {
                float4 x = *(const float4*)&xs[r][done + i];
                a[r] = fmaf(x.x, w0, a[r]);
                a[r] = fmaf(x.y, w1, a[r]);
                a[r] = fmaf(x.z, w2, a[r]);
                a[r] = fmaf(x.w, w3, a[r]);
            }
        }
        for (; i < cur; i++) {
            float w = sw[i][j];
            #pragma unroll
            for (int r = 0; r < 8; r++) a[r] = fmaf(xs[r][done + i], w, a[r]);
        }
        __syncthreads();
        done += cur;
    }

    float* gp = g_part + (size_t)split * BK * OUTD + (size_t)(rg * 8) * OUTD + j;
    #pragma unroll
    for (int r = 0; r < 8; r++) gp[(size_t)r * OUTD] = a[r];
}

// ============================================================
// Kernel 3b: combine partials + GELU + LayerNorm + layer2, SMEM-staged W2.
// grid = 128 blocks (2 rows each), 256 threads.
// ============================================================
__global__ __launch_bounds__(256) void k_mlp2(const float* __restrict__ b1,
                                              const float* __restrict__ ln_g,
                                              const float* __restrict__ ln_b,
                                              const float* __restrict__ W2,
                                              const float* __restrict__ b2,
                                              float* __restrict__ out) {
    const int rg = blockIdx.x;
    const int j  = threadIdx.x;

    __shared__ alignas(16) float hn[2][OUTD];
    __shared__ float sw[32][256];            // 32 KB tile of W2
    __shared__ float red[2][2][8];
    __shared__ float mu_s[2], is_s[2];

    float h[2];
    const float bb = b1[j];
    #pragma unroll
    for (int r = 0; r < 2; r++) {
        const int row = rg * 2 + r;
        float v = g_part[(size_t)row * OUTD + j]
                + g_part[(size_t)(BK + row) * OUTD + j]
                + g_part[(size_t)(2 * BK + row) * OUTD + j]
                + g_part[(size_t)(3 * BK + row) * OUTD + j] + bb;
        v = 0.5f * v * (1.0f + erff(v * 0.7071067811865476f));
        h[r] = v;
    }
    #pragma unroll
    for (int r = 0; r < 2; r++) {
        float s = h[r], s2 = h[r] * h[r];
        #pragma unroll
        for (int off = 16; off; off >>= 1) {
            s  += __shfl_down_sync(0xffffffffu, s, off);
            s2 += __shfl_down_sync(0xffffffffu, s2, off);
        }
        if ((j & 31) == 0) { red[r][0][j >> 5] = s; red[r][1][j >> 5] = s2; }
    }
    __syncthreads();
    if (j < 2) {
        float s = 0.f, s2 = 0.f;
        #pragma unroll
        for (int w = 0; w < 8; w++) { s += red[j][0][w]; s2 += red[j][1][w]; }
        float mu  = s * (1.0f / OUTD);
        float var = s2 * (1.0f / OUTD) - mu * mu;
        mu_s[j] = mu;
        is_s[j] = rsqrtf(var + 1e-5f);
    }
    __syncthreads();
    const float g = ln_g[j], bt = ln_b[j];
    #pragma unroll
    for (int r = 0; r < 2; r++)
        hn[r][j] = (h[r] - mu_s[r]) * is_s[r] * g + bt;
    __syncthreads();

    const float bo = b2[j];
    float o0 = bo, o1 = bo;
    for (int t0 = 0; t0 < OUTD; t0 += 32) {
        #pragma unroll
        for (int i = 0; i < 32; i++)
            sw[i][j] = W2[(size_t)(t0 + i) * OUTD + j];
        __syncthreads();
        #pragma unroll
        for (int i = 0; i < 32; i += 4) {
            float w0 = sw[i + 0][j], w1 = sw[i + 1][j];
            float w2 = sw[i + 2][j], w3 = sw[i + 3][j];
            float4 h0 = *(const float4*)&hn[0][t0 + i];
            float4 h1 = *(const float4*)&hn[1][t0 + i];
            o0 = fmaf(h0.x, w0, o0); o0 = fmaf(h0.y, w1, o0);
            o0 = fmaf(h0.z, w2, o0); o0 = fmaf(h0.w, w3, o0);
            o1 = fmaf(h1.x, w0, o1); o1 = fmaf(h1.y, w1, o1);
            o1 = fmaf(h1.z, w2, o1); o1 = fmaf(h1.w, w3, o1);
        }
        __syncthreads();
    }

    float* op = out + (size_t)(rg * 2) * OUTD + j;
    op[0 * OUTD] = o0;
    op[1 * OUTD] = o1;
}

// ============================================================
extern "C" void kernel_launch(void* const* d_in, const int* in_sizes, int n_in,
                              void* d_out, int out_size) {
    const float* fm    = (const float*)d_in[0];
    const int*   masks = (const int*)d_in[1];
    const void*  cls   = d_in[2];
    const float* emb   = (const float*)d_in[3];
    const float* W1    = (const float*)d_in[4];
    const float* b1    = (const float*)d_in[5];
    const float* lg    = (const float*)d_in[6];
    const float* lb    = (const float*)d_in[7];
    const float* W2    = (const float*)d_in[8];
    const float* b2    = (const float*)d_in[9];
    float* out = (float*)d_out;

    k_init<<<BK, 576>>>(masks, cls, emb);
    k_mask<<<dim3(4, BK), 480>>>(masks);
    k_pool<<<dim3(4, 4, 8), 256>>>(fm);
    k_mlp1<<<dim3(4, 32), 256>>>(W1);
    k_mlp2<<<128, 256>>>(b1, lg, lb, W2, b2, out);
}